// round 14
// baseline (speedup 1.0000x reference)
#include <cuda_runtime.h>
#include <cuda_bf16.h>
#include <math_constants.h>
#include <cstdint>

#define N_ROWS 2048
#define DIM    1024
#define VOC    32000
#define KNN    32

// ---------------- scratch (static device globals: allocation-free) ----------
__device__ __nv_bfloat16 g_featb[(size_t)N_ROWS * 2048]; // [N, 2D] bf16
__device__ __nv_bfloat16 g_wb[(size_t)DIM * 2048];       // mw_w1 bf16
__device__ float g_knnw[N_ROWS * KNN];                   // softmax(-d/bw)
__device__ float g_mixp[N_ROWS];                         // partial mhid.w2 dots

// ---------------- k0: convert mw_w1 to bf16 + zero mixing partials ----------
__global__ void k0_convert_w(const float* __restrict__ w1) {
    int idx = blockIdx.x * blockDim.x + threadIdx.x;     // exactly DIM*2048
    g_wb[idx] = __float2bfloat16(w1[idx]);
    if (idx < N_ROWS) g_mixp[idx] = 0.f;
}

// ---------------- k1: ctx mean + feat(bf16) + bandwidth + knn softmax -------
__global__ __launch_bounds__(256) void k1_ctx(const float* __restrict__ hidden,
                       const float* __restrict__ sh,
                       const float* __restrict__ dist,
                       const float* __restrict__ bw_w,
                       const float* __restrict__ bw_b) {
    int n = blockIdx.x;
    int tid = threadIdx.x;                               // 256 threads
    int d = tid * 4;                                     // each thread: 4 dims
    const float* shrow = sh + (size_t)n * KNN * DIM;
    const float* hrow  = hidden + (size_t)n * DIM;

    float4 acc = make_float4(0.f, 0.f, 0.f, 0.f);
    #pragma unroll
    for (int k = 0; k < KNN; k++) {
        float4 v = *(const float4*)(shrow + k * DIM + d);
        acc.x += v.x; acc.y += v.y; acc.z += v.z; acc.w += v.w;
    }
    const float inv = 1.f / 32.f;
    float4 ctx = make_float4(acc.x * inv, acc.y * inv, acc.z * inv, acc.w * inv);
    float4 h = *(const float4*)(hrow + d);

    __nv_bfloat162* fb = (__nv_bfloat162*)&g_featb[(size_t)n * 2048 + d];
    fb[0] = __nv_bfloat162(__float2bfloat16(h.x), __float2bfloat16(h.y));
    fb[1] = __nv_bfloat162(__float2bfloat16(h.z), __float2bfloat16(h.w));
    __nv_bfloat162* fb2 = (__nv_bfloat162*)&g_featb[(size_t)n * 2048 + DIM + d];
    fb2[0] = __nv_bfloat162(__float2bfloat16(ctx.x), __float2bfloat16(ctx.y));
    fb2[1] = __nv_bfloat162(__float2bfloat16(ctx.z), __float2bfloat16(ctx.w));

    float4 w0 = *(const float4*)(bw_w + d);
    float4 w1 = *(const float4*)(bw_w + DIM + d);
    float bwacc = h.x * w0.x + h.y * w0.y + h.z * w0.z + h.w * w0.w
                + ctx.x * w1.x + ctx.y * w1.y + ctx.z * w1.z + ctx.w * w1.w;

    __shared__ float red[8];
    #pragma unroll
    for (int o = 16; o > 0; o >>= 1) bwacc += __shfl_xor_sync(0xffffffffu, bwacc, o);
    if ((tid & 31) == 0) red[tid >> 5] = bwacc;
    __syncthreads();
    __shared__ float s_bw;
    if (tid == 0) {
        float t = 0.f;
        #pragma unroll
        for (int i = 0; i < 8; i++) t += red[i];
        s_bw = expf(t + bw_b[0]);
    }
    __syncthreads();
    if (tid < 32) {
        float bw = s_bw;
        float t = -dist[n * KNN + tid] / bw;
        float m = t;
        #pragma unroll
        for (int o = 16; o > 0; o >>= 1) m = fmaxf(m, __shfl_xor_sync(0xffffffffu, m, o));
        float e = __expf(t - m);
        float ssum = e;
        #pragma unroll
        for (int o = 16; o > 0; o >>= 1) ssum += __shfl_xor_sync(0xffffffffu, ssum, o);
        g_knnw[n * KNN + tid] = e / ssum;
    }
}

// ---------------- k2: bf16 MMA GEMM, double-buffered smem, 1 sync/iter ------
#define BM 128
#define BN 128
#define BK 32
#define SSTR 40

__device__ __forceinline__ void mma16816(float c[4], const uint32_t a[4], const uint32_t b[2]) {
    asm volatile(
        "mma.sync.aligned.m16n8k16.row.col.f32.bf16.bf16.f32 "
        "{%0,%1,%2,%3}, {%4,%5,%6,%7}, {%8,%9}, {%0,%1,%2,%3};\n"
        : "+f"(c[0]), "+f"(c[1]), "+f"(c[2]), "+f"(c[3])
        : "r"(a[0]), "r"(a[1]), "r"(a[2]), "r"(a[3]), "r"(b[0]), "r"(b[1]));
}

__global__ __launch_bounds__(256) void k2_gemm(const float* __restrict__ b1,
                                               const float* __restrict__ w2) {
    __shared__ __nv_bfloat16 As[2][BM * SSTR];   // 2 x 10240 B
    __shared__ __nv_bfloat16 Bs[2][BN * SSTR];   // 2 x 10240 B
    int tid = threadIdx.x;
    int lane = tid & 31, warp = tid >> 5;
    int wm = warp >> 1, wn = warp & 1;
    int g = lane >> 2, q = lane & 3;
    int bmrow = blockIdx.y * BM;
    int bncol = blockIdx.x * BN;

    float acc[2][8][4];
    #pragma unroll
    for (int i = 0; i < 2; i++)
        #pragma unroll
        for (int j = 0; j < 8; j++)
            #pragma unroll
            for (int c = 0; c < 4; c++) acc[i][j][c] = 0.f;

    int r0 = tid >> 2;               // 0..63
    int cs0 = (tid & 3) * 8;         // 0,8,16,24 (bf16 elems)
    const __nv_bfloat16* Ag  = g_featb + (size_t)(bmrow + r0) * 2048 + cs0;
    const __nv_bfloat16* Ag2 = Ag + (size_t)64 * 2048;
    const __nv_bfloat16* Bg  = g_wb   + (size_t)(bncol + r0) * 2048 + cs0;
    const __nv_bfloat16* Bg2 = Bg + (size_t)64 * 2048;

    // preload tile 0 into buffer 0
    {
        uint4 a0 = *(const uint4*)(Ag);
        uint4 a1 = *(const uint4*)(Ag2);
        uint4 b0 = *(const uint4*)(Bg);
        uint4 b1v = *(const uint4*)(Bg2);
        *(uint4*)&As[0][r0 * SSTR + cs0]        = a0;
        *(uint4*)&As[0][(r0 + 64) * SSTR + cs0] = a1;
        *(uint4*)&Bs[0][r0 * SSTR + cs0]        = b0;
        *(uint4*)&Bs[0][(r0 + 64) * SSTR + cs0] = b1v;
    }
    __syncthreads();

    const int KT = 2048 / BK;        // 64
    for (int kt = 0; kt < KT; kt++) {
        int cur = kt & 1;
        uint4 pa0, pa1, pb0, pb1;
        if (kt + 1 < KT) {           // issue next tile's gmem loads early
            int kb = (kt + 1) * BK;
            pa0 = *(const uint4*)(Ag + kb);
            pa1 = *(const uint4*)(Ag2 + kb);
            pb0 = *(const uint4*)(Bg + kb);
            pb1 = *(const uint4*)(Bg2 + kb);
        }
        // compute on buffer `cur` (overlaps with loads above)
        #pragma unroll
        for (int ks = 0; ks < BK; ks += 16) {
            uint32_t a[2][4], b[8][2];
            #pragma unroll
            for (int mt = 0; mt < 2; mt++) {
                int rr = (wm * 32 + mt * 16 + g) * SSTR + ks + q * 2;
                a[mt][0] = *(const uint32_t*)&As[cur][rr];
                a[mt][1] = *(const uint32_t*)&As[cur][rr + 8 * SSTR];
                a[mt][2] = *(const uint32_t*)&As[cur][rr + 8];
                a[mt][3] = *(const uint32_t*)&As[cur][rr + 8 * SSTR + 8];
            }
            #pragma unroll
            for (int nt = 0; nt < 8; nt++) {
                int rr = (wn * 64 + nt * 8 + g) * SSTR + ks + q * 2;
                b[nt][0] = *(const uint32_t*)&Bs[cur][rr];
                b[nt][1] = *(const uint32_t*)&Bs[cur][rr + 8];
            }
            #pragma unroll
            for (int mt = 0; mt < 2; mt++)
                #pragma unroll
                for (int nt = 0; nt < 8; nt++)
                    mma16816(acc[mt][nt], a[mt], b[nt]);
        }
        // stage next tile into the other buffer (no conflict with readers of cur)
        if (kt + 1 < KT) {
            int nxt = cur ^ 1;
            *(uint4*)&As[nxt][r0 * SSTR + cs0]        = pa0;
            *(uint4*)&As[nxt][(r0 + 64) * SSTR + cs0] = pa1;
            *(uint4*)&Bs[nxt][r0 * SSTR + cs0]        = pb0;
            *(uint4*)&Bs[nxt][(r0 + 64) * SSTR + cs0] = pb1;
        }
        __syncthreads();             // single barrier per K-tile
    }

    // Epilogue: relu(acc + b1), dot with w2, accumulate per-row mixing partials.
    #pragma unroll
    for (int mt = 0; mt < 2; mt++) {
        int row = bmrow + wm * 32 + mt * 16 + g;
        float prow = 0.f, prow8 = 0.f;
        #pragma unroll
        for (int nt = 0; nt < 8; nt++) {
            int col = bncol + wn * 64 + nt * 8 + q * 2;
            float bb0 = b1[col], bb1 = b1[col + 1];
            float w20 = w2[col], w21 = w2[col + 1];
            float v0 = fmaxf(acc[mt][nt][0] + bb0, 0.f);
            float v1 = fmaxf(acc[mt][nt][1] + bb1, 0.f);
            float v2 = fmaxf(acc[mt][nt][2] + bb0, 0.f);
            float v3 = fmaxf(acc[mt][nt][3] + bb1, 0.f);
            prow  = fmaf(v0, w20, fmaf(v1, w21, prow));
            prow8 = fmaf(v2, w20, fmaf(v3, w21, prow8));
        }
        prow  += __shfl_xor_sync(0xffffffffu, prow, 1);
        prow  += __shfl_xor_sync(0xffffffffu, prow, 2);
        prow8 += __shfl_xor_sync(0xffffffffu, prow8, 1);
        prow8 += __shfl_xor_sync(0xffffffffu, prow8, 2);
        if (q == 0) {
            atomicAdd(&g_mixp[row], prow);
            atomicAdd(&g_mixp[row + 8], prow8);
        }
    }
}

// ---------------- k4: 3-pass smem-resident with log-shortcut ----------------
// pass1: pure DRAM->smem copy (no MUFU in the DRAM pass — R3-vs-R7 lesson).
// pass2: sum of exp over smem (registers only, NO smem write-back; unnorm-
// alized exp is fp32-safe, R5/R8-certified). pass3: out = x + log(coef)
// (R8-certified shortcut, no per-element log). Patch tail exact fp32.
__global__ __launch_bounds__(1024) void k4_out(const float* __restrict__ logits,
                                               const int* __restrict__ tok,
                                               const float* __restrict__ b2,
                                               float* __restrict__ out) {
    extern __shared__ float sm[];          // VOC floats = 128000 B
    __shared__ float red[32];
    __shared__ float s_lc, s_coef, s_mix;
    int n = blockIdx.x;
    int tid = threadIdx.x;
    int lane = tid & 31, warp = tid >> 5;
    const float* lrow = logits + (size_t)n * VOC;
    float* orow = out + (size_t)n * VOC;

    // pass 1: pure copy DRAM -> smem (float4, L2-cached)
    #pragma unroll 8
    for (int i = tid * 4; i < VOC; i += 4096) {
        float4 x = __ldcg((const float4*)(lrow + i));
        *(float4*)&sm[i] = x;
    }
    __syncthreads();

    // pass 2: s = sum of exp(x) over smem (no write-back)
    float s = 0.f;
    #pragma unroll 8
    for (int i = tid * 4; i < VOC; i += 4096) {
        float4 x = *(float4*)&sm[i];
        s += (__expf(x.x) + __expf(x.y)) + (__expf(x.z) + __expf(x.w));
    }
    #pragma unroll
    for (int o = 16; o > 0; o >>= 1) s += __shfl_xor_sync(0xffffffffu, s, o);
    if (lane == 0) red[warp] = s;
    __syncthreads();
    if (warp == 0) {
        s = red[lane];
        #pragma unroll
        for (int o = 16; o > 0; o >>= 1) s += __shfl_xor_sync(0xffffffffu, s, o);
        if (lane == 0) {
            float mix = 1.f / (1.f + expf(-(g_mixp[n] + b2[0])));
            float coef = (1.f - mix) / s;
            s_mix = mix;
            s_coef = coef;
            s_lc = logf(coef);
        }
    }
    __syncthreads();
    float lc = s_lc;

    // pass 3: out = x + log(coef)  (FADD only, streaming store)
    #pragma unroll 8
    for (int i = tid * 4; i < VOC; i += 4096) {
        float4 x = *(float4*)&sm[i];
        x.x += lc; x.y += lc; x.z += lc; x.w += lc;
        __stcs((float4*)(orow + i), x);
    }
    __syncthreads();   // order row writes before the patch overwrites

    // patch the <=32 scattered tokens with the exact fp32 formula
    if (tid < KNN) {
        int t = tok[n * KNN + tid];
        float w = g_knnw[n * KNN + tid] * s_mix;
        unsigned grp = __match_any_sync(0xffffffffu, t);
        float tot = 0.f;
        #pragma unroll
        for (int j = 0; j < 32; j++)
            if (grp & (1u << j)) tot += __shfl_sync(0xffffffffu, w, j);
        if ((grp & ((1u << tid) - 1u)) == 0) {           // lowest lane of group
            float e = __expf(sm[t]);                     // exact x from smem
            orow[t] = __logf(fmaf(e, s_coef, tot + 1e-10f));
        }
    }
}

// ---------------- launch -----------------------------------------------------
extern "C" void kernel_launch(void* const* d_in, const int* in_sizes, int n_in,
                              void* d_out, int out_size) {
    const float* hidden = (const float*)d_in[0];
    const float* logits = (const float*)d_in[1];
    const float* dist   = (const float*)d_in[2];
    const int*   tok    = (const int*)d_in[3];
    const float* sh     = (const float*)d_in[4];
    const float* bw_w   = (const float*)d_in[5];
    const float* bw_b   = (const float*)d_in[6];
    const float* mw_w1  = (const float*)d_in[7];
    const float* mw_b1  = (const float*)d_in[8];
    const float* mw_w2  = (const float*)d_in[9];
    const float* mw_b2  = (const float*)d_in[10];
    float* out = (float*)d_out;

    cudaFuncSetAttribute(k4_out, cudaFuncAttributeMaxDynamicSharedMemorySize,
                         VOC * (int)sizeof(float));

    k0_convert_w<<<2048, 1024>>>(mw_w1);
    k1_ctx<<<N_ROWS, 256>>>(hidden, sh, dist, bw_w, bw_b);
    dim3 g2(DIM / BN, N_ROWS / BM);   // (8, 16)
    k2_gemm<<<g2, 256>>>(mw_b1, mw_w2);
    k4_out<<<N_ROWS, 1024, VOC * sizeof(float)>>>(logits, tok, mw_b2, out);
}

// round 15
// speedup vs baseline: 3.7749x; 3.7749x over previous
#include <cuda_runtime.h>
#include <cuda_bf16.h>
#include <math_constants.h>
#include <cstdint>

#define N_ROWS 2048
#define DIM    1024
#define VOC    32000
#define KNN    32

// ---------------- scratch (static device globals: allocation-free) ----------
__device__ __nv_bfloat16 g_featb[(size_t)N_ROWS * 2048]; // [N, 2D] bf16
__device__ __nv_bfloat16 g_wb[(size_t)DIM * 2048];       // mw_w1 bf16
__device__ float g_knnw[N_ROWS * KNN];                   // softmax(-d/bw)
__device__ float g_mixp[N_ROWS];                         // partial mhid.w2 dots

// ---------------- k0: convert mw_w1 to bf16 + zero mixing partials ----------
__global__ void k0_convert_w(const float* __restrict__ w1) {
    int idx = blockIdx.x * blockDim.x + threadIdx.x;     // exactly DIM*2048
    g_wb[idx] = __float2bfloat16(w1[idx]);
    if (idx < N_ROWS) g_mixp[idx] = 0.f;
}

// ---------------- k1: ctx mean + feat(bf16) + bandwidth + knn softmax -------
__global__ __launch_bounds__(256) void k1_ctx(const float* __restrict__ hidden,
                       const float* __restrict__ sh,
                       const float* __restrict__ dist,
                       const float* __restrict__ bw_w,
                       const float* __restrict__ bw_b) {
    int n = blockIdx.x;
    int tid = threadIdx.x;                               // 256 threads
    int d = tid * 4;                                     // each thread: 4 dims
    const float* shrow = sh + (size_t)n * KNN * DIM;
    const float* hrow  = hidden + (size_t)n * DIM;

    float4 acc = make_float4(0.f, 0.f, 0.f, 0.f);
    #pragma unroll
    for (int k = 0; k < KNN; k++) {
        float4 v = *(const float4*)(shrow + k * DIM + d);
        acc.x += v.x; acc.y += v.y; acc.z += v.z; acc.w += v.w;
    }
    const float inv = 1.f / 32.f;
    float4 ctx = make_float4(acc.x * inv, acc.y * inv, acc.z * inv, acc.w * inv);
    float4 h = *(const float4*)(hrow + d);

    __nv_bfloat162* fb = (__nv_bfloat162*)&g_featb[(size_t)n * 2048 + d];
    fb[0] = __nv_bfloat162(__float2bfloat16(h.x), __float2bfloat16(h.y));
    fb[1] = __nv_bfloat162(__float2bfloat16(h.z), __float2bfloat16(h.w));
    __nv_bfloat162* fb2 = (__nv_bfloat162*)&g_featb[(size_t)n * 2048 + DIM + d];
    fb2[0] = __nv_bfloat162(__float2bfloat16(ctx.x), __float2bfloat16(ctx.y));
    fb2[1] = __nv_bfloat162(__float2bfloat16(ctx.z), __float2bfloat16(ctx.w));

    float4 w0 = *(const float4*)(bw_w + d);
    float4 w1 = *(const float4*)(bw_w + DIM + d);
    float bwacc = h.x * w0.x + h.y * w0.y + h.z * w0.z + h.w * w0.w
                + ctx.x * w1.x + ctx.y * w1.y + ctx.z * w1.z + ctx.w * w1.w;

    __shared__ float red[8];
    #pragma unroll
    for (int o = 16; o > 0; o >>= 1) bwacc += __shfl_xor_sync(0xffffffffu, bwacc, o);
    if ((tid & 31) == 0) red[tid >> 5] = bwacc;
    __syncthreads();
    __shared__ float s_bw;
    if (tid == 0) {
        float t = 0.f;
        #pragma unroll
        for (int i = 0; i < 8; i++) t += red[i];
        s_bw = expf(t + bw_b[0]);
    }
    __syncthreads();
    if (tid < 32) {
        float bw = s_bw;
        float t = -dist[n * KNN + tid] / bw;
        float m = t;
        #pragma unroll
        for (int o = 16; o > 0; o >>= 1) m = fmaxf(m, __shfl_xor_sync(0xffffffffu, m, o));
        float e = __expf(t - m);
        float ssum = e;
        #pragma unroll
        for (int o = 16; o > 0; o >>= 1) ssum += __shfl_xor_sync(0xffffffffu, ssum, o);
        g_knnw[n * KNN + tid] = e / ssum;
    }
}

// ---------------- k2: bf16 MMA GEMM, 3-stage cp.async pipeline --------------
#define BM 128
#define BN 128
#define BK 32
#define SSTR 40
#define NSTAGE 3

__device__ __forceinline__ void mma16816(float c[4], const uint32_t a[4], const uint32_t b[2]) {
    asm volatile(
        "mma.sync.aligned.m16n8k16.row.col.f32.bf16.bf16.f32 "
        "{%0,%1,%2,%3}, {%4,%5,%6,%7}, {%8,%9}, {%0,%1,%2,%3};\n"
        : "+f"(c[0]), "+f"(c[1]), "+f"(c[2]), "+f"(c[3])
        : "r"(a[0]), "r"(a[1]), "r"(a[2]), "r"(a[3]), "r"(b[0]), "r"(b[1]));
}

__device__ __forceinline__ void cp_async16(uint32_t smem_addr, const void* gptr) {
    asm volatile("cp.async.cg.shared.global [%0], [%1], 16;\n"
                 :: "r"(smem_addr), "l"(gptr));
}
__device__ __forceinline__ void cp_commit() {
    asm volatile("cp.async.commit_group;\n");
}
template <int N>
__device__ __forceinline__ void cp_wait() {
    asm volatile("cp.async.wait_group %0;\n" :: "n"(N));
}

__global__ __launch_bounds__(256) void k2_gemm(const float* __restrict__ b1,
                                               const float* __restrict__ w2) {
    __shared__ __nv_bfloat16 As[NSTAGE][BM * SSTR];   // 3 x 10240 B
    __shared__ __nv_bfloat16 Bs[NSTAGE][BN * SSTR];   // 3 x 10240 B
    int tid = threadIdx.x;
    int lane = tid & 31, warp = tid >> 5;
    int wm = warp >> 1, wn = warp & 1;
    int g = lane >> 2, q = lane & 3;
    int bmrow = blockIdx.y * BM;
    int bncol = blockIdx.x * BN;

    float acc[2][8][4];
    #pragma unroll
    for (int i = 0; i < 2; i++)
        #pragma unroll
        for (int j = 0; j < 8; j++)
            #pragma unroll
            for (int c = 0; c < 4; c++) acc[i][j][c] = 0.f;

    int r0 = tid >> 2;               // 0..63
    int cs0 = (tid & 3) * 8;         // 0,8,16,24 (bf16 elems)
    const __nv_bfloat16* Ag  = g_featb + (size_t)(bmrow + r0) * 2048 + cs0;
    const __nv_bfloat16* Ag2 = Ag + (size_t)64 * 2048;
    const __nv_bfloat16* Bg  = g_wb   + (size_t)(bncol + r0) * 2048 + cs0;
    const __nv_bfloat16* Bg2 = Bg + (size_t)64 * 2048;

    uint32_t sA  = (uint32_t)__cvta_generic_to_shared(&As[0][0]);
    uint32_t sB  = (uint32_t)__cvta_generic_to_shared(&Bs[0][0]);
    const uint32_t stageA = BM * SSTR * 2;   // bytes per A stage
    const uint32_t stageB = BN * SSTR * 2;
    uint32_t offA  = (r0 * SSTR + cs0) * 2;
    uint32_t offA2 = ((r0 + 64) * SSTR + cs0) * 2;

    // prefetch tiles 0 and 1
    #pragma unroll
    for (int p = 0; p < 2; p++) {
        int kb = p * BK;
        cp_async16(sA + p * stageA + offA,  Ag  + kb);
        cp_async16(sA + p * stageA + offA2, Ag2 + kb);
        cp_async16(sB + p * stageB + offA,  Bg  + kb);
        cp_async16(sB + p * stageB + offA2, Bg2 + kb);
        cp_commit();
    }

    const int KT = 2048 / BK;        // 64
    for (int kt = 0; kt < KT; kt++) {
        if (kt + 1 < KT) cp_wait<1>(); else cp_wait<0>();
        __syncthreads();             // tile kt resident for all threads
        int cur = kt % NSTAGE;

        #pragma unroll
        for (int ks = 0; ks < BK; ks += 16) {
            uint32_t a[2][4], b[8][2];
            #pragma unroll
            for (int mt = 0; mt < 2; mt++) {
                int rr = (wm * 32 + mt * 16 + g) * SSTR + ks + q * 2;
                a[mt][0] = *(const uint32_t*)&As[cur][rr];
                a[mt][1] = *(const uint32_t*)&As[cur][rr + 8 * SSTR];
                a[mt][2] = *(const uint32_t*)&As[cur][rr + 8];
                a[mt][3] = *(const uint32_t*)&As[cur][rr + 8 * SSTR + 8];
            }
            #pragma unroll
            for (int nt = 0; nt < 8; nt++) {
                int rr = (wn * 64 + nt * 8 + g) * SSTR + ks + q * 2;
                b[nt][0] = *(const uint32_t*)&Bs[cur][rr];
                b[nt][1] = *(const uint32_t*)&Bs[cur][rr + 8];
            }
            #pragma unroll
            for (int mt = 0; mt < 2; mt++)
                #pragma unroll
                for (int nt = 0; nt < 8; nt++)
                    mma16816(acc[mt][nt], a[mt], b[nt]);
        }

        // prefetch tile kt+2 into stage (kt+2)%3 — untouched by current
        // compute (cur) and pending tile (kt+1). The loop-top sync of the
        // NEXT iteration orders this store after all compute on that stage.
        if (kt + 2 < KT) {
            int nxt = (kt + 2) % NSTAGE;
            int kb = (kt + 2) * BK;
            cp_async16(sA + nxt * stageA + offA,  Ag  + kb);
            cp_async16(sA + nxt * stageA + offA2, Ag2 + kb);
            cp_async16(sB + nxt * stageB + offA,  Bg  + kb);
            cp_async16(sB + nxt * stageB + offA2, Bg2 + kb);
            cp_commit();
        }
    }

    // Epilogue: relu(acc + b1), dot with w2, accumulate per-row mixing partials.
    #pragma unroll
    for (int mt = 0; mt < 2; mt++) {
        int row = bmrow + wm * 32 + mt * 16 + g;
        float prow = 0.f, prow8 = 0.f;
        #pragma unroll
        for (int nt = 0; nt < 8; nt++) {
            int col = bncol + wn * 64 + nt * 8 + q * 2;
            float bb0 = b1[col], bb1 = b1[col + 1];
            float w20 = w2[col], w21 = w2[col + 1];
            float v0 = fmaxf(acc[mt][nt][0] + bb0, 0.f);
            float v1 = fmaxf(acc[mt][nt][1] + bb1, 0.f);
            float v2 = fmaxf(acc[mt][nt][2] + bb0, 0.f);
            float v3 = fmaxf(acc[mt][nt][3] + bb1, 0.f);
            prow  = fmaf(v0, w20, fmaf(v1, w21, prow));
            prow8 = fmaf(v2, w20, fmaf(v3, w21, prow8));
        }
        prow  += __shfl_xor_sync(0xffffffffu, prow, 1);
        prow  += __shfl_xor_sync(0xffffffffu, prow, 2);
        prow8 += __shfl_xor_sync(0xffffffffu, prow8, 1);
        prow8 += __shfl_xor_sync(0xffffffffu, prow8, 2);
        if (q == 0) {
            atomicAdd(&g_mixp[row], prow);
            atomicAdd(&g_mixp[row + 8], prow8);
        }
    }
}

// ---------------- k4: R13-exact vectorized 3-phase (measured 153.2us) -------
__global__ __launch_bounds__(1024) void k4_out(const float* __restrict__ logits,
                                               const int* __restrict__ tok,
                                               const float* __restrict__ b2,
                                               float* __restrict__ out) {
    extern __shared__ float sm[];          // VOC floats = 128000 B
    __shared__ float red[32];
    __shared__ float s_M, s_coef, s_mix;
    int n = blockIdx.x;
    int tid = threadIdx.x;
    int lane = tid & 31, warp = tid >> 5;
    const float* lrow = logits + (size_t)n * VOC;

    // pass 1: load (float4, L2-cached) + running max
    float m = -CUDART_INF_F;
    #pragma unroll 8
    for (int i = tid * 4; i < VOC; i += 4096) {
        float4 x = __ldcg((const float4*)(lrow + i));
        *(float4*)&sm[i] = x;
        m = fmaxf(m, fmaxf(fmaxf(x.x, x.y), fmaxf(x.z, x.w)));
    }
    #pragma unroll
    for (int o = 16; o > 0; o >>= 1) m = fmaxf(m, __shfl_xor_sync(0xffffffffu, m, o));
    if (lane == 0) red[warp] = m;
    __syncthreads();
    if (warp == 0) {
        m = red[lane];
        #pragma unroll
        for (int o = 16; o > 0; o >>= 1) m = fmaxf(m, __shfl_xor_sync(0xffffffffu, m, o));
        if (lane == 0) s_M = m;
    }
    __syncthreads();
    float M = s_M;

    // pass 2: e = exp(x - M) into smem, accumulate sum
    float s = 0.f;
    #pragma unroll 8
    for (int i = tid * 4; i < VOC; i += 4096) {
        float4 x = *(float4*)&sm[i];
        float4 e;
        e.x = __expf(x.x - M); e.y = __expf(x.y - M);
        e.z = __expf(x.z - M); e.w = __expf(x.w - M);
        *(float4*)&sm[i] = e;
        s += (e.x + e.y) + (e.z + e.w);
    }
    #pragma unroll
    for (int o = 16; o > 0; o >>= 1) s += __shfl_xor_sync(0xffffffffu, s, o);
    if (lane == 0) red[warp] = s;
    __syncthreads();
    if (warp == 0) {
        s = red[lane];
        #pragma unroll
        for (int o = 16; o > 0; o >>= 1) s += __shfl_xor_sync(0xffffffffu, s, o);
        if (lane == 0) {
            float mix = 1.f / (1.f + expf(-(g_mixp[n] + b2[0])));
            s_mix = mix;
            s_coef = (1.f - mix) / s;   // prob = coef * e
        }
    }
    __syncthreads();
    float coef = s_coef;

    // sparse scatter in exp-domain: coef*(e + w/coef) = (1-mix)p + mix*knnw
    if (tid < KNN) {
        float w = g_knnw[n * KNN + tid] * s_mix;
        atomicAdd(&sm[tok[n * KNN + tid]], w / coef);
    }
    __syncthreads();

    // pass 3: log + streaming store
    float* orow = out + (size_t)n * VOC;
    #pragma unroll 8
    for (int i = tid * 4; i < VOC; i += 4096) {
        float4 e = *(float4*)&sm[i];
        float4 o4;
        o4.x = __logf(fmaf(e.x, coef, 1e-10f));
        o4.y = __logf(fmaf(e.y, coef, 1e-10f));
        o4.z = __logf(fmaf(e.z, coef, 1e-10f));
        o4.w = __logf(fmaf(e.w, coef, 1e-10f));
        __stcs((float4*)(orow + i), o4);
    }
}

// ---------------- launch -----------------------------------------------------
extern "C" void kernel_launch(void* const* d_in, const int* in_sizes, int n_in,
                              void* d_out, int out_size) {
    const float* hidden = (const float*)d_in[0];
    const float* logits = (const float*)d_in[1];
    const float* dist   = (const float*)d_in[2];
    const int*   tok    = (const int*)d_in[3];
    const float* sh     = (const float*)d_in[4];
    const float* bw_w   = (const float*)d_in[5];
    const float* bw_b   = (const float*)d_in[6];
    const float* mw_w1  = (const float*)d_in[7];
    const float* mw_b1  = (const float*)d_in[8];
    const float* mw_w2  = (const float*)d_in[9];
    const float* mw_b2  = (const float*)d_in[10];
    float* out = (float*)d_out;

    cudaFuncSetAttribute(k4_out, cudaFuncAttributeMaxDynamicSharedMemorySize,
                         VOC * (int)sizeof(float));

    k0_convert_w<<<2048, 1024>>>(mw_w1);
    k1_ctx<<<N_ROWS, 256>>>(hidden, sh, dist, bw_w, bw_b);
    dim3 g2(DIM / BN, N_ROWS / BM);   // (8, 16)
    k2_gemm<<<g2, 256>>>(mw_b1, mw_w2);
    k4_out<<<N_ROWS, 1024, VOC * sizeof(float)>>>(logits, tok, mw_b2, out);
}

// round 16
// speedup vs baseline: 4.0501x; 1.0729x over previous
#include <cuda_runtime.h>
#include <cuda_bf16.h>
#include <math_constants.h>
#include <cstdint>

#define N_ROWS 2048
#define DIM    1024
#define VOC    32000
#define KNN    32

// ---------------- scratch (static device globals: allocation-free) ----------
__device__ __nv_bfloat16 g_featb[(size_t)N_ROWS * 2048]; // [N, 2D] bf16
__device__ __nv_bfloat16 g_wb[(size_t)DIM * 2048];       // mw_w1 bf16
__device__ float g_knnw[N_ROWS * KNN];                   // softmax(-d/bw)
__device__ float g_mixp[N_ROWS];                         // partial mhid.w2 dots

// ---------------- k0: convert mw_w1 to bf16 + zero mixing partials ----------
__global__ void k0_convert_w(const float* __restrict__ w1) {
    int idx = blockIdx.x * blockDim.x + threadIdx.x;     // exactly DIM*2048
    g_wb[idx] = __float2bfloat16(w1[idx]);
    if (idx < N_ROWS) g_mixp[idx] = 0.f;
}

// ---------------- k1: ctx mean + feat(bf16) + bandwidth + knn softmax -------
__global__ __launch_bounds__(256) void k1_ctx(const float* __restrict__ hidden,
                       const float* __restrict__ sh,
                       const float* __restrict__ dist,
                       const float* __restrict__ bw_w,
                       const float* __restrict__ bw_b) {
    int n = blockIdx.x;
    int tid = threadIdx.x;                               // 256 threads
    int d = tid * 4;                                     // each thread: 4 dims
    const float* shrow = sh + (size_t)n * KNN * DIM;
    const float* hrow  = hidden + (size_t)n * DIM;

    float4 acc = make_float4(0.f, 0.f, 0.f, 0.f);
    #pragma unroll
    for (int k = 0; k < KNN; k++) {
        float4 v = *(const float4*)(shrow + k * DIM + d);
        acc.x += v.x; acc.y += v.y; acc.z += v.z; acc.w += v.w;
    }
    const float inv = 1.f / 32.f;
    float4 ctx = make_float4(acc.x * inv, acc.y * inv, acc.z * inv, acc.w * inv);
    float4 h = *(const float4*)(hrow + d);

    __nv_bfloat162* fb = (__nv_bfloat162*)&g_featb[(size_t)n * 2048 + d];
    fb[0] = __nv_bfloat162(__float2bfloat16(h.x), __float2bfloat16(h.y));
    fb[1] = __nv_bfloat162(__float2bfloat16(h.z), __float2bfloat16(h.w));
    __nv_bfloat162* fb2 = (__nv_bfloat162*)&g_featb[(size_t)n * 2048 + DIM + d];
    fb2[0] = __nv_bfloat162(__float2bfloat16(ctx.x), __float2bfloat16(ctx.y));
    fb2[1] = __nv_bfloat162(__float2bfloat16(ctx.z), __float2bfloat16(ctx.w));

    float4 w0 = *(const float4*)(bw_w + d);
    float4 w1 = *(const float4*)(bw_w + DIM + d);
    float bwacc = h.x * w0.x + h.y * w0.y + h.z * w0.z + h.w * w0.w
                + ctx.x * w1.x + ctx.y * w1.y + ctx.z * w1.z + ctx.w * w1.w;

    __shared__ float red[8];
    #pragma unroll
    for (int o = 16; o > 0; o >>= 1) bwacc += __shfl_xor_sync(0xffffffffu, bwacc, o);
    if ((tid & 31) == 0) red[tid >> 5] = bwacc;
    __syncthreads();
    __shared__ float s_bw;
    if (tid == 0) {
        float t = 0.f;
        #pragma unroll
        for (int i = 0; i < 8; i++) t += red[i];
        s_bw = expf(t + bw_b[0]);
    }
    __syncthreads();
    if (tid < 32) {
        float bw = s_bw;
        float t = -dist[n * KNN + tid] / bw;
        float m = t;
        #pragma unroll
        for (int o = 16; o > 0; o >>= 1) m = fmaxf(m, __shfl_xor_sync(0xffffffffu, m, o));
        float e = __expf(t - m);
        float ssum = e;
        #pragma unroll
        for (int o = 16; o > 0; o >>= 1) ssum += __shfl_xor_sync(0xffffffffu, ssum, o);
        g_knnw[n * KNN + tid] = e / ssum;
    }
}

// ---------------- k2: bf16 MMA GEMM, 3-stage cp.async pipeline --------------
#define BM 128
#define BN 128
#define BK 32
#define SSTR 40
#define NSTAGE 3

__device__ __forceinline__ void mma16816(float c[4], const uint32_t a[4], const uint32_t b[2]) {
    asm volatile(
        "mma.sync.aligned.m16n8k16.row.col.f32.bf16.bf16.f32 "
        "{%0,%1,%2,%3}, {%4,%5,%6,%7}, {%8,%9}, {%0,%1,%2,%3};\n"
        : "+f"(c[0]), "+f"(c[1]), "+f"(c[2]), "+f"(c[3])
        : "r"(a[0]), "r"(a[1]), "r"(a[2]), "r"(a[3]), "r"(b[0]), "r"(b[1]));
}

__device__ __forceinline__ void cp_async16(uint32_t smem_addr, const void* gptr) {
    asm volatile("cp.async.cg.shared.global [%0], [%1], 16;\n"
                 :: "r"(smem_addr), "l"(gptr));
}
__device__ __forceinline__ void cp_commit() {
    asm volatile("cp.async.commit_group;\n");
}
template <int N>
__device__ __forceinline__ void cp_wait() {
    asm volatile("cp.async.wait_group %0;\n" :: "n"(N));
}

__global__ __launch_bounds__(256) void k2_gemm(const float* __restrict__ b1,
                                               const float* __restrict__ w2) {
    __shared__ __nv_bfloat16 As[NSTAGE][BM * SSTR];   // 3 x 10240 B
    __shared__ __nv_bfloat16 Bs[NSTAGE][BN * SSTR];   // 3 x 10240 B
    int tid = threadIdx.x;
    int lane = tid & 31, warp = tid >> 5;
    int wm = warp >> 1, wn = warp & 1;
    int g = lane >> 2, q = lane & 3;
    int bmrow = blockIdx.y * BM;
    int bncol = blockIdx.x * BN;

    float acc[2][8][4];
    #pragma unroll
    for (int i = 0; i < 2; i++)
        #pragma unroll
        for (int j = 0; j < 8; j++)
            #pragma unroll
            for (int c = 0; c < 4; c++) acc[i][j][c] = 0.f;

    int r0 = tid >> 2;               // 0..63
    int cs0 = (tid & 3) * 8;         // 0,8,16,24 (bf16 elems)
    const __nv_bfloat16* Ag  = g_featb + (size_t)(bmrow + r0) * 2048 + cs0;
    const __nv_bfloat16* Ag2 = Ag + (size_t)64 * 2048;
    const __nv_bfloat16* Bg  = g_wb   + (size_t)(bncol + r0) * 2048 + cs0;
    const __nv_bfloat16* Bg2 = Bg + (size_t)64 * 2048;

    uint32_t sA  = (uint32_t)__cvta_generic_to_shared(&As[0][0]);
    uint32_t sB  = (uint32_t)__cvta_generic_to_shared(&Bs[0][0]);
    const uint32_t stageA = BM * SSTR * 2;   // bytes per A stage
    const uint32_t stageB = BN * SSTR * 2;
    uint32_t offA  = (r0 * SSTR + cs0) * 2;
    uint32_t offA2 = ((r0 + 64) * SSTR + cs0) * 2;

    // prefetch tiles 0 and 1
    #pragma unroll
    for (int p = 0; p < 2; p++) {
        int kb = p * BK;
        cp_async16(sA + p * stageA + offA,  Ag  + kb);
        cp_async16(sA + p * stageA + offA2, Ag2 + kb);
        cp_async16(sB + p * stageB + offA,  Bg  + kb);
        cp_async16(sB + p * stageB + offA2, Bg2 + kb);
        cp_commit();
    }

    const int KT = 2048 / BK;        // 64
    for (int kt = 0; kt < KT; kt++) {
        if (kt + 1 < KT) cp_wait<1>(); else cp_wait<0>();
        __syncthreads();             // tile kt resident for all threads
        int cur = kt % NSTAGE;

        #pragma unroll
        for (int ks = 0; ks < BK; ks += 16) {
            uint32_t a[2][4], b[8][2];
            #pragma unroll
            for (int mt = 0; mt < 2; mt++) {
                int rr = (wm * 32 + mt * 16 + g) * SSTR + ks + q * 2;
                a[mt][0] = *(const uint32_t*)&As[cur][rr];
                a[mt][1] = *(const uint32_t*)&As[cur][rr + 8 * SSTR];
                a[mt][2] = *(const uint32_t*)&As[cur][rr + 8];
                a[mt][3] = *(const uint32_t*)&As[cur][rr + 8 * SSTR + 8];
            }
            #pragma unroll
            for (int nt = 0; nt < 8; nt++) {
                int rr = (wn * 64 + nt * 8 + g) * SSTR + ks + q * 2;
                b[nt][0] = *(const uint32_t*)&Bs[cur][rr];
                b[nt][1] = *(const uint32_t*)&Bs[cur][rr + 8];
            }
            #pragma unroll
            for (int mt = 0; mt < 2; mt++)
                #pragma unroll
                for (int nt = 0; nt < 8; nt++)
                    mma16816(acc[mt][nt], a[mt], b[nt]);
        }

        // prefetch tile kt+2 into stage (kt+2)%3
        if (kt + 2 < KT) {
            int nxt = (kt + 2) % NSTAGE;
            int kb = (kt + 2) * BK;
            cp_async16(sA + nxt * stageA + offA,  Ag  + kb);
            cp_async16(sA + nxt * stageA + offA2, Ag2 + kb);
            cp_async16(sB + nxt * stageB + offA,  Bg  + kb);
            cp_async16(sB + nxt * stageB + offA2, Bg2 + kb);
            cp_commit();
        }
    }

    // Epilogue: relu(acc + b1), dot with w2, accumulate per-row mixing partials.
    #pragma unroll
    for (int mt = 0; mt < 2; mt++) {
        int row = bmrow + wm * 32 + mt * 16 + g;
        float prow = 0.f, prow8 = 0.f;
        #pragma unroll
        for (int nt = 0; nt < 8; nt++) {
            int col = bncol + wn * 64 + nt * 8 + q * 2;
            float bb0 = b1[col], bb1 = b1[col + 1];
            float w20 = w2[col], w21 = w2[col + 1];
            float v0 = fmaxf(acc[mt][nt][0] + bb0, 0.f);
            float v1 = fmaxf(acc[mt][nt][1] + bb1, 0.f);
            float v2 = fmaxf(acc[mt][nt][2] + bb0, 0.f);
            float v3 = fmaxf(acc[mt][nt][3] + bb1, 0.f);
            prow  = fmaf(v0, w20, fmaf(v1, w21, prow));
            prow8 = fmaf(v2, w20, fmaf(v3, w21, prow8));
        }
        prow  += __shfl_xor_sync(0xffffffffu, prow, 1);
        prow  += __shfl_xor_sync(0xffffffffu, prow, 2);
        prow8 += __shfl_xor_sync(0xffffffffu, prow8, 1);
        prow8 += __shfl_xor_sync(0xffffffffu, prow8, 2);
        if (q == 0) {
            atomicAdd(&g_mixp[row], prow);
            atomicAdd(&g_mixp[row + 8], prow8);
        }
    }
}

// ---------------- k4: row-pair software pipeline -----------------------------
// Each CTA handles rows (2b, 2b+1). Pass3(row A) is fused with Pass1(row B):
// per element, read e_A from smem, write out_A (DRAM write), load x_B (DRAM
// read), overwrite smem. Read and write streams hit the DRAM controller
// concurrently instead of in alternating phases. Math identical to R13/R15.
__global__ __launch_bounds__(1024) void k4_out(const float* __restrict__ logits,
                                               const int* __restrict__ tok,
                                               const float* __restrict__ b2,
                                               float* __restrict__ out) {
    extern __shared__ float sm[];          // VOC floats = 128000 B
    __shared__ float red[32];
    __shared__ float s_M, s_coef, s_mix;
    int tid = threadIdx.x;
    int lane = tid & 31, warp = tid >> 5;
    int nA = blockIdx.x * 2;
    int nB = nA + 1;
    const float* lrowA = logits + (size_t)nA * VOC;
    const float* lrowB = logits + (size_t)nB * VOC;
    float* orowA = out + (size_t)nA * VOC;
    float* orowB = out + (size_t)nB * VOC;

    // ---- pass 1 (A): load + running max ----
    float m = -CUDART_INF_F;
    #pragma unroll 8
    for (int i = tid * 4; i < VOC; i += 4096) {
        float4 x = __ldcg((const float4*)(lrowA + i));
        *(float4*)&sm[i] = x;
        m = fmaxf(m, fmaxf(fmaxf(x.x, x.y), fmaxf(x.z, x.w)));
    }
    #pragma unroll
    for (int o = 16; o > 0; o >>= 1) m = fmaxf(m, __shfl_xor_sync(0xffffffffu, m, o));
    if (lane == 0) red[warp] = m;
    __syncthreads();
    if (warp == 0) {
        m = red[lane];
        #pragma unroll
        for (int o = 16; o > 0; o >>= 1) m = fmaxf(m, __shfl_xor_sync(0xffffffffu, m, o));
        if (lane == 0) s_M = m;
    }
    __syncthreads();
    float MA = s_M;

    // ---- pass 2 (A): e = exp(x - M) into smem, sum ----
    float s = 0.f;
    #pragma unroll 8
    for (int i = tid * 4; i < VOC; i += 4096) {
        float4 x = *(float4*)&sm[i];
        float4 e;
        e.x = __expf(x.x - MA); e.y = __expf(x.y - MA);
        e.z = __expf(x.z - MA); e.w = __expf(x.w - MA);
        *(float4*)&sm[i] = e;
        s += (e.x + e.y) + (e.z + e.w);
    }
    #pragma unroll
    for (int o = 16; o > 0; o >>= 1) s += __shfl_xor_sync(0xffffffffu, s, o);
    if (lane == 0) red[warp] = s;
    __syncthreads();
    if (warp == 0) {
        s = red[lane];
        #pragma unroll
        for (int o = 16; o > 0; o >>= 1) s += __shfl_xor_sync(0xffffffffu, s, o);
        if (lane == 0) {
            float mix = 1.f / (1.f + expf(-(g_mixp[nA] + b2[0])));
            s_mix = mix;
            s_coef = (1.f - mix) / s;
        }
    }
    __syncthreads();
    float coefA = s_coef;

    // scatter A (exp-domain)
    if (tid < KNN) {
        float w = g_knnw[nA * KNN + tid] * s_mix;
        atomicAdd(&sm[tok[nA * KNN + tid]], w / coefA);
    }
    __syncthreads();

    // ---- fused: pass 3 (A) + pass 1 (B) ----
    // DRAM write (out_A) and DRAM read (logits_B) in the same loop body.
    m = -CUDART_INF_F;
    #pragma unroll 4
    for (int i = tid * 4; i < VOC; i += 4096) {
        float4 e = *(float4*)&sm[i];
        float4 x = __ldcg((const float4*)(lrowB + i));
        float4 o4;
        o4.x = __logf(fmaf(e.x, coefA, 1e-10f));
        o4.y = __logf(fmaf(e.y, coefA, 1e-10f));
        o4.z = __logf(fmaf(e.z, coefA, 1e-10f));
        o4.w = __logf(fmaf(e.w, coefA, 1e-10f));
        __stcs((float4*)(orowA + i), o4);
        *(float4*)&sm[i] = x;              // own cell: read-then-overwrite safe
        m = fmaxf(m, fmaxf(fmaxf(x.x, x.y), fmaxf(x.z, x.w)));
    }
    #pragma unroll
    for (int o = 16; o > 0; o >>= 1) m = fmaxf(m, __shfl_xor_sync(0xffffffffu, m, o));
    if (lane == 0) red[warp] = m;
    __syncthreads();
    if (warp == 0) {
        m = red[lane];
        #pragma unroll
        for (int o = 16; o > 0; o >>= 1) m = fmaxf(m, __shfl_xor_sync(0xffffffffu, m, o));
        if (lane == 0) s_M = m;
    }
    __syncthreads();
    float MB = s_M;

    // ---- pass 2 (B): exp + sum ----
    s = 0.f;
    #pragma unroll 8
    for (int i = tid * 4; i < VOC; i += 4096) {
        float4 x = *(float4*)&sm[i];
        float4 e;
        e.x = __expf(x.x - MB); e.y = __expf(x.y - MB);
        e.z = __expf(x.z - MB); e.w = __expf(x.w - MB);
        *(float4*)&sm[i] = e;
        s += (e.x + e.y) + (e.z + e.w);
    }
    #pragma unroll
    for (int o = 16; o > 0; o >>= 1) s += __shfl_xor_sync(0xffffffffu, s, o);
    if (lane == 0) red[warp] = s;
    __syncthreads();
    if (warp == 0) {
        s = red[lane];
        #pragma unroll
        for (int o = 16; o > 0; o >>= 1) s += __shfl_xor_sync(0xffffffffu, s, o);
        if (lane == 0) {
            float mix = 1.f / (1.f + expf(-(g_mixp[nB] + b2[0])));
            s_mix = mix;
            s_coef = (1.f - mix) / s;
        }
    }
    __syncthreads();
    float coefB = s_coef;

    // scatter B (exp-domain)
    if (tid < KNN) {
        float w = g_knnw[nB * KNN + tid] * s_mix;
        atomicAdd(&sm[tok[nB * KNN + tid]], w / coefB);
    }
    __syncthreads();

    // ---- pass 3 (B): log + streaming store ----
    #pragma unroll 8
    for (int i = tid * 4; i < VOC; i += 4096) {
        float4 e = *(float4*)&sm[i];
        float4 o4;
        o4.x = __logf(fmaf(e.x, coefB, 1e-10f));
        o4.y = __logf(fmaf(e.y, coefB, 1e-10f));
        o4.z = __logf(fmaf(e.z, coefB, 1e-10f));
        o4.w = __logf(fmaf(e.w, coefB, 1e-10f));
        __stcs((float4*)(orowB + i), o4);
    }
}

// ---------------- launch -----------------------------------------------------
extern "C" void kernel_launch(void* const* d_in, const int* in_sizes, int n_in,
                              void* d_out, int out_size) {
    const float* hidden = (const float*)d_in[0];
    const float* logits = (const float*)d_in[1];
    const float* dist   = (const float*)d_in[2];
    const int*   tok    = (const int*)d_in[3];
    const float* sh     = (const float*)d_in[4];
    const float* bw_w   = (const float*)d_in[5];
    const float* bw_b   = (const float*)d_in[6];
    const float* mw_w1  = (const float*)d_in[7];
    const float* mw_b1  = (const float*)d_in[8];
    const float* mw_w2  = (const float*)d_in[9];
    const float* mw_b2  = (const float*)d_in[10];
    float* out = (float*)d_out;

    cudaFuncSetAttribute(k4_out, cudaFuncAttributeMaxDynamicSharedMemorySize,
                         VOC * (int)sizeof(float));

    k0_convert_w<<<2048, 1024>>>(mw_w1);
    k1_ctx<<<N_ROWS, 256>>>(hidden, sh, dist, bw_w, bw_b);
    dim3 g2(DIM / BN, N_ROWS / BM);   // (8, 16)
    k2_gemm<<<g2, 256>>>(mw_b1, mw_w2);
    k4_out<<<N_ROWS / 2, 1024, VOC * sizeof(float)>>>(logits, tok, mw_b2, out);
}

// round 17
// speedup vs baseline: 4.3355x; 1.0705x over previous
#include <cuda_runtime.h>
#include <cuda_bf16.h>
#include <math_constants.h>
#include <cstdint>

#define N_ROWS 2048
#define DIM    1024
#define VOC    32000
#define KNN    32
#define K4GRID 148

// ---------------- scratch (static device globals: allocation-free) ----------
__device__ __nv_bfloat16 g_featb[(size_t)N_ROWS * 2048]; // [N, 2D] bf16
__device__ __nv_bfloat16 g_wb[(size_t)DIM * 2048];       // mw_w1 bf16
__device__ float g_knnw[N_ROWS * KNN];                   // softmax(-d/bw)
__device__ float g_mixp[N_ROWS];                         // partial mhid.w2 dots

// ---------------- k0: convert mw_w1 to bf16 + zero mixing partials ----------
__global__ void k0_convert_w(const float* __restrict__ w1) {
    int idx = blockIdx.x * blockDim.x + threadIdx.x;     // exactly DIM*2048
    g_wb[idx] = __float2bfloat16(w1[idx]);
    if (idx < N_ROWS) g_mixp[idx] = 0.f;
}

// ---------------- k1: ctx mean + feat(bf16) + bandwidth + knn softmax -------
__global__ __launch_bounds__(256) void k1_ctx(const float* __restrict__ hidden,
                       const float* __restrict__ sh,
                       const float* __restrict__ dist,
                       const float* __restrict__ bw_w,
                       const float* __restrict__ bw_b) {
    int n = blockIdx.x;
    int tid = threadIdx.x;                               // 256 threads
    int d = tid * 4;                                     // each thread: 4 dims
    const float* shrow = sh + (size_t)n * KNN * DIM;
    const float* hrow  = hidden + (size_t)n * DIM;

    float4 acc = make_float4(0.f, 0.f, 0.f, 0.f);
    #pragma unroll
    for (int k = 0; k < KNN; k++) {
        float4 v = *(const float4*)(shrow + k * DIM + d);
        acc.x += v.x; acc.y += v.y; acc.z += v.z; acc.w += v.w;
    }
    const float inv = 1.f / 32.f;
    float4 ctx = make_float4(acc.x * inv, acc.y * inv, acc.z * inv, acc.w * inv);
    float4 h = *(const float4*)(hrow + d);

    __nv_bfloat162* fb = (__nv_bfloat162*)&g_featb[(size_t)n * 2048 + d];
    fb[0] = __nv_bfloat162(__float2bfloat16(h.x), __float2bfloat16(h.y));
    fb[1] = __nv_bfloat162(__float2bfloat16(h.z), __float2bfloat16(h.w));
    __nv_bfloat162* fb2 = (__nv_bfloat162*)&g_featb[(size_t)n * 2048 + DIM + d];
    fb2[0] = __nv_bfloat162(__float2bfloat16(ctx.x), __float2bfloat16(ctx.y));
    fb2[1] = __nv_bfloat162(__float2bfloat16(ctx.z), __float2bfloat16(ctx.w));

    float4 w0 = *(const float4*)(bw_w + d);
    float4 w1 = *(const float4*)(bw_w + DIM + d);
    float bwacc = h.x * w0.x + h.y * w0.y + h.z * w0.z + h.w * w0.w
                + ctx.x * w1.x + ctx.y * w1.y + ctx.z * w1.z + ctx.w * w1.w;

    __shared__ float red[8];
    #pragma unroll
    for (int o = 16; o > 0; o >>= 1) bwacc += __shfl_xor_sync(0xffffffffu, bwacc, o);
    if ((tid & 31) == 0) red[tid >> 5] = bwacc;
    __syncthreads();
    __shared__ float s_bw;
    if (tid == 0) {
        float t = 0.f;
        #pragma unroll
        for (int i = 0; i < 8; i++) t += red[i];
        s_bw = expf(t + bw_b[0]);
    }
    __syncthreads();
    if (tid < 32) {
        float bw = s_bw;
        float t = -dist[n * KNN + tid] / bw;
        float m = t;
        #pragma unroll
        for (int o = 16; o > 0; o >>= 1) m = fmaxf(m, __shfl_xor_sync(0xffffffffu, m, o));
        float e = __expf(t - m);
        float ssum = e;
        #pragma unroll
        for (int o = 16; o > 0; o >>= 1) ssum += __shfl_xor_sync(0xffffffffu, ssum, o);
        g_knnw[n * KNN + tid] = e / ssum;
    }
}

// ---------------- k2: bf16 MMA GEMM, 3-stage cp.async pipeline --------------
#define BM 128
#define BN 128
#define BK 32
#define SSTR 40
#define NSTAGE 3

__device__ __forceinline__ void mma16816(float c[4], const uint32_t a[4], const uint32_t b[2]) {
    asm volatile(
        "mma.sync.aligned.m16n8k16.row.col.f32.bf16.bf16.f32 "
        "{%0,%1,%2,%3}, {%4,%5,%6,%7}, {%8,%9}, {%0,%1,%2,%3};\n"
        : "+f"(c[0]), "+f"(c[1]), "+f"(c[2]), "+f"(c[3])
        : "r"(a[0]), "r"(a[1]), "r"(a[2]), "r"(a[3]), "r"(b[0]), "r"(b[1]));
}

__device__ __forceinline__ void cp_async16(uint32_t smem_addr, const void* gptr) {
    asm volatile("cp.async.cg.shared.global [%0], [%1], 16;\n"
                 :: "r"(smem_addr), "l"(gptr));
}
__device__ __forceinline__ void cp_commit() {
    asm volatile("cp.async.commit_group;\n");
}
template <int N>
__device__ __forceinline__ void cp_wait() {
    asm volatile("cp.async.wait_group %0;\n" :: "n"(N));
}

__global__ __launch_bounds__(256) void k2_gemm(const float* __restrict__ b1,
                                               const float* __restrict__ w2) {
    __shared__ __nv_bfloat16 As[NSTAGE][BM * SSTR];   // 3 x 10240 B
    __shared__ __nv_bfloat16 Bs[NSTAGE][BN * SSTR];   // 3 x 10240 B
    int tid = threadIdx.x;
    int lane = tid & 31, warp = tid >> 5;
    int wm = warp >> 1, wn = warp & 1;
    int g = lane >> 2, q = lane & 3;
    int bmrow = blockIdx.y * BM;
    int bncol = blockIdx.x * BN;

    float acc[2][8][4];
    #pragma unroll
    for (int i = 0; i < 2; i++)
        #pragma unroll
        for (int j = 0; j < 8; j++)
            #pragma unroll
            for (int c = 0; c < 4; c++) acc[i][j][c] = 0.f;

    int r0 = tid >> 2;               // 0..63
    int cs0 = (tid & 3) * 8;         // 0,8,16,24 (bf16 elems)
    const __nv_bfloat16* Ag  = g_featb + (size_t)(bmrow + r0) * 2048 + cs0;
    const __nv_bfloat16* Ag2 = Ag + (size_t)64 * 2048;
    const __nv_bfloat16* Bg  = g_wb   + (size_t)(bncol + r0) * 2048 + cs0;
    const __nv_bfloat16* Bg2 = Bg + (size_t)64 * 2048;

    uint32_t sA  = (uint32_t)__cvta_generic_to_shared(&As[0][0]);
    uint32_t sB  = (uint32_t)__cvta_generic_to_shared(&Bs[0][0]);
    const uint32_t stageA = BM * SSTR * 2;   // bytes per A stage
    const uint32_t stageB = BN * SSTR * 2;
    uint32_t offA  = (r0 * SSTR + cs0) * 2;
    uint32_t offA2 = ((r0 + 64) * SSTR + cs0) * 2;

    // prefetch tiles 0 and 1
    #pragma unroll
    for (int p = 0; p < 2; p++) {
        int kb = p * BK;
        cp_async16(sA + p * stageA + offA,  Ag  + kb);
        cp_async16(sA + p * stageA + offA2, Ag2 + kb);
        cp_async16(sB + p * stageB + offA,  Bg  + kb);
        cp_async16(sB + p * stageB + offA2, Bg2 + kb);
        cp_commit();
    }

    const int KT = 2048 / BK;        // 64
    for (int kt = 0; kt < KT; kt++) {
        if (kt + 1 < KT) cp_wait<1>(); else cp_wait<0>();
        __syncthreads();             // tile kt resident for all threads
        int cur = kt % NSTAGE;

        #pragma unroll
        for (int ks = 0; ks < BK; ks += 16) {
            uint32_t a[2][4], b[8][2];
            #pragma unroll
            for (int mt = 0; mt < 2; mt++) {
                int rr = (wm * 32 + mt * 16 + g) * SSTR + ks + q * 2;
                a[mt][0] = *(const uint32_t*)&As[cur][rr];
                a[mt][1] = *(const uint32_t*)&As[cur][rr + 8 * SSTR];
                a[mt][2] = *(const uint32_t*)&As[cur][rr + 8];
                a[mt][3] = *(const uint32_t*)&As[cur][rr + 8 * SSTR + 8];
            }
            #pragma unroll
            for (int nt = 0; nt < 8; nt++) {
                int rr = (wn * 64 + nt * 8 + g) * SSTR + ks + q * 2;
                b[nt][0] = *(const uint32_t*)&Bs[cur][rr];
                b[nt][1] = *(const uint32_t*)&Bs[cur][rr + 8];
            }
            #pragma unroll
            for (int mt = 0; mt < 2; mt++)
                #pragma unroll
                for (int nt = 0; nt < 8; nt++)
                    mma16816(acc[mt][nt], a[mt], b[nt]);
        }

        // prefetch tile kt+2 into stage (kt+2)%3
        if (kt + 2 < KT) {
            int nxt = (kt + 2) % NSTAGE;
            int kb = (kt + 2) * BK;
            cp_async16(sA + nxt * stageA + offA,  Ag  + kb);
            cp_async16(sA + nxt * stageA + offA2, Ag2 + kb);
            cp_async16(sB + nxt * stageB + offA,  Bg  + kb);
            cp_async16(sB + nxt * stageB + offA2, Bg2 + kb);
            cp_commit();
        }
    }

    // Epilogue: relu(acc + b1), dot with w2, accumulate per-row mixing partials.
    #pragma unroll
    for (int mt = 0; mt < 2; mt++) {
        int row = bmrow + wm * 32 + mt * 16 + g;
        float prow = 0.f, prow8 = 0.f;
        #pragma unroll
        for (int nt = 0; nt < 8; nt++) {
            int col = bncol + wn * 64 + nt * 8 + q * 2;
            float bb0 = b1[col], bb1 = b1[col + 1];
            float w20 = w2[col], w21 = w2[col + 1];
            float v0 = fmaxf(acc[mt][nt][0] + bb0, 0.f);
            float v1 = fmaxf(acc[mt][nt][1] + bb1, 0.f);
            float v2 = fmaxf(acc[mt][nt][2] + bb0, 0.f);
            float v3 = fmaxf(acc[mt][nt][3] + bb1, 0.f);
            prow  = fmaf(v0, w20, fmaf(v1, w21, prow));
            prow8 = fmaf(v2, w20, fmaf(v3, w21, prow8));
        }
        prow  += __shfl_xor_sync(0xffffffffu, prow, 1);
        prow  += __shfl_xor_sync(0xffffffffu, prow, 2);
        prow8 += __shfl_xor_sync(0xffffffffu, prow8, 1);
        prow8 += __shfl_xor_sync(0xffffffffu, prow8, 2);
        if (q == 0) {
            atomicAdd(&g_mixp[row], prow);
            atomicAdd(&g_mixp[row + 8], prow8);
        }
    }
}

// ---------------- k4: persistent row pipeline (deep R/W overlap) ------------
// 148 CTAs (one per SM, single wave). Each CTA walks rows bid, bid+148, ...
// Steady state per row: exp+sum -> scatter -> FUSED [pass3(cur) write ||
// pass1(next) read]. Only the first read and the last write are unoverlapped:
// R+1 DRAM phases for R rows instead of 2R. Math identical to R13/R16.
__global__ __launch_bounds__(1024) void k4_out(const float* __restrict__ logits,
                                               const int* __restrict__ tok,
                                               const float* __restrict__ b2,
                                               float* __restrict__ out) {
    extern __shared__ float sm[];          // VOC floats = 128000 B
    __shared__ float red[32];
    __shared__ float s_M, s_coef, s_mix;
    int tid = threadIdx.x;
    int lane = tid & 31, warp = tid >> 5;
    int n = blockIdx.x;

    // prologue: pass 1 for first row — load + running max
    {
        const float* lrow = logits + (size_t)n * VOC;
        float m = -CUDART_INF_F;
        #pragma unroll 8
        for (int i = tid * 4; i < VOC; i += 4096) {
            float4 x = __ldcg((const float4*)(lrow + i));
            *(float4*)&sm[i] = x;
            m = fmaxf(m, fmaxf(fmaxf(x.x, x.y), fmaxf(x.z, x.w)));
        }
        #pragma unroll
        for (int o = 16; o > 0; o >>= 1) m = fmaxf(m, __shfl_xor_sync(0xffffffffu, m, o));
        if (lane == 0) red[warp] = m;
        __syncthreads();
        if (warp == 0) {
            m = red[lane];
            #pragma unroll
            for (int o = 16; o > 0; o >>= 1) m = fmaxf(m, __shfl_xor_sync(0xffffffffu, m, o));
            if (lane == 0) s_M = m;
        }
        __syncthreads();
    }

    for (;;) {
        float M = s_M;
        const float* lrow = logits + (size_t)n * VOC;
        float* orow = out + (size_t)n * VOC;

        // pass 2: e = exp(x - M) into smem, accumulate sum
        float s = 0.f;
        #pragma unroll 8
        for (int i = tid * 4; i < VOC; i += 4096) {
            float4 x = *(float4*)&sm[i];
            float4 e;
            e.x = __expf(x.x - M); e.y = __expf(x.y - M);
            e.z = __expf(x.z - M); e.w = __expf(x.w - M);
            *(float4*)&sm[i] = e;
            s += (e.x + e.y) + (e.z + e.w);
        }
        #pragma unroll
        for (int o = 16; o > 0; o >>= 1) s += __shfl_xor_sync(0xffffffffu, s, o);
        if (lane == 0) red[warp] = s;
        __syncthreads();
        if (warp == 0) {
            s = red[lane];
            #pragma unroll
            for (int o = 16; o > 0; o >>= 1) s += __shfl_xor_sync(0xffffffffu, s, o);
            if (lane == 0) {
                float mix = 1.f / (1.f + expf(-(g_mixp[n] + b2[0])));
                s_mix = mix;
                s_coef = (1.f - mix) / s;
            }
        }
        __syncthreads();
        float coef = s_coef;

        // sparse scatter in exp-domain
        if (tid < KNN) {
            float w = g_knnw[n * KNN + tid] * s_mix;
            atomicAdd(&sm[tok[n * KNN + tid]], w / coef);
        }
        __syncthreads();

        int nn = n + K4GRID;
        if (nn < N_ROWS) {
            // steady state: FUSED pass3(n) + pass1(nn)
            const float* lrowN = logits + (size_t)nn * VOC;
            float m = -CUDART_INF_F;
            #pragma unroll 4
            for (int i = tid * 4; i < VOC; i += 4096) {
                float4 e = *(float4*)&sm[i];
                float4 x = __ldcg((const float4*)(lrowN + i));
                float4 o4;
                o4.x = __logf(fmaf(e.x, coef, 1e-10f));
                o4.y = __logf(fmaf(e.y, coef, 1e-10f));
                o4.z = __logf(fmaf(e.z, coef, 1e-10f));
                o4.w = __logf(fmaf(e.w, coef, 1e-10f));
                __stcs((float4*)(orow + i), o4);
                *(float4*)&sm[i] = x;          // own cell: read-then-overwrite
                m = fmaxf(m, fmaxf(fmaxf(x.x, x.y), fmaxf(x.z, x.w)));
            }
            #pragma unroll
            for (int o = 16; o > 0; o >>= 1) m = fmaxf(m, __shfl_xor_sync(0xffffffffu, m, o));
            if (lane == 0) red[warp] = m;
            __syncthreads();
            if (warp == 0) {
                m = red[lane];
                #pragma unroll
                for (int o = 16; o > 0; o >>= 1) m = fmaxf(m, __shfl_xor_sync(0xffffffffu, m, o));
                if (lane == 0) s_M = m;
            }
            __syncthreads();
            n = nn;
        } else {
            // epilogue: plain pass 3 for the last row
            #pragma unroll 8
            for (int i = tid * 4; i < VOC; i += 4096) {
                float4 e = *(float4*)&sm[i];
                float4 o4;
                o4.x = __logf(fmaf(e.x, coef, 1e-10f));
                o4.y = __logf(fmaf(e.y, coef, 1e-10f));
                o4.z = __logf(fmaf(e.z, coef, 1e-10f));
                o4.w = __logf(fmaf(e.w, coef, 1e-10f));
                __stcs((float4*)(orow + i), o4);
            }
            break;
        }
    }
}

// ---------------- launch -----------------------------------------------------
extern "C" void kernel_launch(void* const* d_in, const int* in_sizes, int n_in,
                              void* d_out, int out_size) {
    const float* hidden = (const float*)d_in[0];
    const float* logits = (const float*)d_in[1];
    const float* dist   = (const float*)d_in[2];
    const int*   tok    = (const int*)d_in[3];
    const float* sh     = (const float*)d_in[4];
    const float* bw_w   = (const float*)d_in[5];
    const float* bw_b   = (const float*)d_in[6];
    const float* mw_w1  = (const float*)d_in[7];
    const float* mw_b1  = (const float*)d_in[8];
    const float* mw_w2  = (const float*)d_in[9];
    const float* mw_b2  = (const float*)d_in[10];
    float* out = (float*)d_out;

    cudaFuncSetAttribute(k4_out, cudaFuncAttributeMaxDynamicSharedMemorySize,
                         VOC * (int)sizeof(float));

    k0_convert_w<<<2048, 1024>>>(mw_w1);
    k1_ctx<<<N_ROWS, 256>>>(hidden, sh, dist, bw_w, bw_b);
    dim3 g2(DIM / BN, N_ROWS / BM);   // (8, 16)
    k2_gemm<<<g2, 256>>>(mw_b1, mw_w2);
    k4_out<<<K4GRID, 1024, VOC * sizeof(float)>>>(logits, tok, mw_b2, out);
}